// round 1
// baseline (speedup 1.0000x reference)
#include <cuda_runtime.h>

#define NN 16384
#define NE 65536
#define NG 64
#define NZ 10
#define CH 128

// ---------------- scratch (device globals; no allocations) ----------------
__device__ float d_sh[NE * 16];
__device__ float d_rad[NE * 8];
__device__ float d_tpw[(size_t)NE * 512];      // 128 MB
__device__ float d_up[NN * CH];
__device__ float d_scb[NN * CH];
__device__ float d_msg[(size_t)NN * 16 * CH];  // 32 MB
__device__ float d_Amat[(size_t)NN * 16 * CH]; // 32 MB
__device__ float d_nfA[NN * CH];
__device__ float d_nfB[NN * CH];
__device__ int   d_species[NN];
__device__ int   d_count[NN];
__device__ int   d_offsets[NN + 1];
__device__ int   d_cursor[NN];
__device__ int   d_perm[NE];
__device__ int   d_scount[NZ];
__device__ int   d_soff[NZ + 1];
__device__ int   d_scursor[NZ];
__device__ int   d_sperm[NN];
__device__ float d_gcnt[NG];

__device__ __forceinline__ float silu(float x) {
    return x / (1.f + __expf(-x));
}

// ---------------- init / zero ----------------
__global__ void k_zero() {
    int i = blockIdx.x * blockDim.x + threadIdx.x;
    if (i < NN) d_count[i] = 0;
    if (i < NZ) d_scount[i] = 0;
    if (i < NG) d_gcnt[i] = 0.f;
}

// species + initial node feats = W_embed[s]/sqrt(10)
__global__ void k_node_init(const float* __restrict__ x,
                            const float* __restrict__ W_embed) {
    int tid = blockIdx.x * blockDim.x + threadIdx.x;
    if (tid >= NN * CH) return;
    int n = tid >> 7, k = tid & 127;
    const float* xr = x + n * NZ;
    int s = 0;
    float best = xr[0];
#pragma unroll
    for (int z = 1; z < NZ; z++) {
        float v = xr[z];
        if (v > best) { best = v; s = z; }
    }
    if (k == 0) {
        d_species[n] = s;
        atomicAdd(&d_scount[s], 1);
    }
    d_nfA[tid] = W_embed[s * CH + k] * 0.31622776601683794f;
}

// ---------------- edge geometry: SH + radial basis ----------------
__global__ void k_edge_geom(const float* __restrict__ pos,
                            const int* __restrict__ edge_index) {
    int e = blockIdx.x * blockDim.x + threadIdx.x;
    if (e >= NE) return;
    int j = edge_index[e];
    int i = edge_index[NE + e];
    float dx = pos[j * 3 + 0] - pos[i * 3 + 0];
    float dy = pos[j * 3 + 1] - pos[i * 3 + 1];
    float dz = pos[j * 3 + 2] - pos[i * 3 + 2];
    float r2 = dx * dx + dy * dy + dz * dz + 1e-12f;
    float r = sqrtf(r2);
    float inv = 1.f / r;
    float X = dx * inv, Y = dy * inv, Z = dz * inv;
    float x2 = X * X, y2 = Y * Y, z2 = Z * Z;

    const float s3 = 1.7320508075688772f;
    const float s15 = 3.872983346207417f;
    const float s5 = 2.23606797749979f;
    const float s35_8 = 2.091650066335189f;
    const float s105 = 10.246950765959598f;
    const float s21_8 = 1.6201851746019651f;
    const float s7 = 2.6457513110645907f;

    float sh[16];
    sh[0] = 1.f;
    sh[1] = s3 * X; sh[2] = s3 * Y; sh[3] = s3 * Z;
    sh[4] = s15 * X * Y;
    sh[5] = s15 * Y * Z;
    sh[6] = 0.5f * s5 * (3.f * z2 - 1.f);
    sh[7] = s15 * X * Z;
    sh[8] = 0.5f * s15 * (x2 - y2);
    sh[9] = s35_8 * Y * (3.f * x2 - y2);
    sh[10] = s105 * X * Y * Z;
    sh[11] = s21_8 * Y * (5.f * z2 - 1.f);
    sh[12] = 0.5f * s7 * Z * (5.f * z2 - 3.f);
    sh[13] = s21_8 * X * (5.f * z2 - 1.f);
    sh[14] = 0.5f * s105 * Z * (x2 - y2);
    sh[15] = s35_8 * X * (x2 - 3.f * y2);
#pragma unroll
    for (int q = 0; q < 4; q++)
        *(float4*)&d_sh[e * 16 + q * 4] = *(float4*)&sh[q * 4];

    // radial embedding with polynomial cutoff (p=5)
    float u = r * 0.2f;  // r / R_MAX
    float u2 = u * u;
    float u5 = u2 * u2 * u;
    float f = 1.f - 21.f * u5 + 35.f * u5 * u - 15.f * u5 * u2;
    if (u >= 1.f) f = 0.f;
    float coef = 0.6324555320336759f * inv * f;  // sqrt(2/5)/r*f
    float rad[8];
#pragma unroll
    for (int nb = 1; nb <= 8; nb++)
        rad[nb - 1] = coef * sinpif((float)nb * u);
    *(float4*)&d_rad[e * 8] = *(float4*)&rad[0];
    *(float4*)&d_rad[e * 8 + 4] = *(float4*)&rad[4];
}

// ---------------- CSR build ----------------
__global__ void k_hist(const int* __restrict__ edge_index) {
    int e = blockIdx.x * blockDim.x + threadIdx.x;
    if (e >= NE) return;
    atomicAdd(&d_count[edge_index[NE + e]], 1);
}

__global__ void k_scan() {
    __shared__ int sh[1024];
    int T = threadIdx.x;
    int base = T * 16;
    int loc[16];
    int s = 0;
#pragma unroll
    for (int q = 0; q < 16; q++) { loc[q] = d_count[base + q]; s += loc[q]; }
    sh[T] = s;
    __syncthreads();
    for (int off = 1; off < 1024; off <<= 1) {
        int v = (T >= off) ? sh[T - off] : 0;
        __syncthreads();
        sh[T] += v;
        __syncthreads();
    }
    int excl = sh[T] - s;
#pragma unroll
    for (int q = 0; q < 16; q++) {
        d_offsets[base + q] = excl;
        d_cursor[base + q] = excl;
        excl += loc[q];
    }
    if (T == 1023) d_offsets[NN] = sh[1023];
    if (T == 0) {
        int a = 0;
        for (int z = 0; z < NZ; z++) {
            d_soff[z] = a; d_scursor[z] = a; a += d_scount[z];
        }
        d_soff[NZ] = a;
    }
}

__global__ void k_scatter(const int* __restrict__ edge_index) {
    int e = blockIdx.x * blockDim.x + threadIdx.x;
    if (e >= NE) return;
    int i = edge_index[NE + e];
    int p = atomicAdd(&d_cursor[i], 1);
    d_perm[p] = e;
}

__global__ void k_sscatter() {
    int n = blockIdx.x * blockDim.x + threadIdx.x;
    if (n >= NN) return;
    int s = d_species[n];
    int p = atomicAdd(&d_scursor[s], 1);
    d_sperm[p] = n;
}

// ---------------- up = nf @ W_up / sqrt(128) ----------------
__global__ void k_up(int t, const float* __restrict__ W_up) {
    extern __shared__ float sm[];
    float* Wsh = sm;          // 16384
    float* fsh = sm + 16384;  // 16*128
    const float* nf = (t == 0) ? d_nfA : d_nfB;
    const float* W = W_up + t * CH * CH;
    int k = threadIdx.x;
    for (int i = k; i < CH * CH; i += 128) Wsh[i] = W[i];
    int n0 = blockIdx.x * 16;
    for (int r = 0; r < 16; r++)
        fsh[r * CH + k] = nf[(n0 + r) * CH + k];
    __syncthreads();
    for (int r = 0; r < 16; r++) {
        float acc = 0.f;
        const float* f = fsh + r * CH;
#pragma unroll 8
        for (int c = 0; c < CH; c++) acc += f[c] * Wsh[c * CH + k];
        d_up[(n0 + r) * CH + k] = acc * 0.08838834764831845f;
    }
}

// ---------------- sc (species-bucketed skip) ----------------
__global__ void k_sc(int t, const float* __restrict__ W_skip) {
    int z = blockIdx.y;
    int lo = d_soff[z], hi = d_soff[z + 1];
    int n0 = lo + blockIdx.x * 16;
    if (n0 >= hi) return;
    extern __shared__ float sm[];
    float* Wsh = sm;
    float* fsh = sm + 16384;
    __shared__ int nsh[16];
    const float* nf = (t == 0) ? d_nfA : d_nfB;
    const float* W = W_skip + ((size_t)t * NZ + z) * CH * CH;
    int k = threadIdx.x;
    for (int i = k; i < CH * CH; i += 128) Wsh[i] = W[i];
    int cnt = min(16, hi - n0);
    for (int r = 0; r < cnt; r++) {
        int node = d_sperm[n0 + r];
        if (k == 0) nsh[r] = node;
        fsh[r * CH + k] = nf[node * CH + k];
    }
    __syncthreads();
    for (int r = 0; r < cnt; r++) {
        float acc = 0.f;
        const float* f = fsh + r * CH;
#pragma unroll 8
        for (int c = 0; c < CH; c++) acc += f[c] * Wsh[c * CH + k];
        d_scb[nsh[r] * CH + k] = acc * 0.027950849718747372f;  // 1/sqrt(1280)
    }
}

// ---------------- radial MLP (per edge) -> tpw ----------------
__global__ void __launch_bounds__(256) k_radial(
    int t, const float* __restrict__ Wr0, const float* __restrict__ Wr1,
    const float* __restrict__ Wr2, const float* __restrict__ Wr3) {
    extern __shared__ float sm[];
    float* w0 = sm;              // 512
    float* w1 = w0 + 512;        // 4096
    float* w2 = w1 + 4096;       // 4096
    float* w3 = w2 + 4096;       // 32768
    float* radsh = w3 + 32768;   // 32
    float* hA = radsh + 32;      // 256
    float* hB = hA + 256;        // 256

    const float* W0 = Wr0 + t * 8 * 64;
    const float* W1 = Wr1 + t * 64 * 64;
    const float* W2 = Wr2 + t * 64 * 64;
    const float* W3 = Wr3 + t * 64 * 512;
    int tid = threadIdx.x;
    for (int i = tid; i < 512; i += 256) w0[i] = W0[i];
    for (int i = tid; i < 4096; i += 256) w1[i] = W1[i];
    for (int i = tid; i < 4096; i += 256) w2[i] = W2[i];
    for (int i = tid; i < 32768; i += 256) w3[i] = W3[i];
    __syncthreads();

    int eo = tid >> 6, o = tid & 63;
    int ebase0 = blockIdx.x * 128;
    for (int it = 0; it < 32; it++) {
        int ebase = ebase0 + it * 4;
        if (tid < 32) radsh[tid] = d_rad[(ebase + (tid >> 3)) * 8 + (tid & 7)];
        __syncthreads();
        // layer 0: 8 -> 64
        float acc = 0.f;
#pragma unroll
        for (int c = 0; c < 8; c++) acc += radsh[eo * 8 + c] * w0[c * 64 + o];
        hA[eo * 64 + o] = silu(acc * 0.3535533905932738f);
        __syncthreads();
        // layer 1: 64 -> 64
        acc = 0.f;
#pragma unroll 8
        for (int c = 0; c < 64; c++) acc += hA[eo * 64 + c] * w1[c * 64 + o];
        hB[eo * 64 + o] = silu(acc * 0.125f);
        __syncthreads();
        // layer 2: 64 -> 64
        acc = 0.f;
#pragma unroll 8
        for (int c = 0; c < 64; c++) acc += hB[eo * 64 + c] * w2[c * 64 + o];
        hA[eo * 64 + o] = silu(acc * 0.125f);
        __syncthreads();
        // layer 3: 64 -> 512, 8 outputs per thread
        float a[8] = {0.f, 0.f, 0.f, 0.f, 0.f, 0.f, 0.f, 0.f};
#pragma unroll 4
        for (int c = 0; c < 64; c++) {
            float hv = hA[eo * 64 + c];
            float4 wa = *(const float4*)&w3[c * 512 + 8 * o];
            float4 wb = *(const float4*)&w3[c * 512 + 8 * o + 4];
            a[0] += hv * wa.x; a[1] += hv * wa.y; a[2] += hv * wa.z; a[3] += hv * wa.w;
            a[4] += hv * wb.x; a[5] += hv * wb.y; a[6] += hv * wb.z; a[7] += hv * wb.w;
        }
        size_t e = (size_t)(ebase + eo);
        float4 oa = make_float4(a[0] * 0.125f, a[1] * 0.125f, a[2] * 0.125f, a[3] * 0.125f);
        float4 ob = make_float4(a[4] * 0.125f, a[5] * 0.125f, a[6] * 0.125f, a[7] * 0.125f);
        *(float4*)&d_tpw[e * 512 + 8 * o] = oa;
        *(float4*)&d_tpw[e * 512 + 8 * o + 4] = ob;
        __syncthreads();
    }
}

// ---------------- gather: msg[n,m,k] (CSR, registers) ----------------
__global__ void k_gather(const int* __restrict__ edge_index) {
    int n = blockIdx.x;
    int k = threadIdx.x;
    __shared__ float shv[16];
    int lo = d_offsets[n], hi = d_offsets[n + 1];
    float acc[16];
#pragma unroll
    for (int m = 0; m < 16; m++) acc[m] = 0.f;
    for (int p = lo; p < hi; p++) {
        int e = d_perm[p];
        if (k < 16) shv[k] = d_sh[e * 16 + k];
        __syncthreads();
        int j = edge_index[e];
        float u = d_up[j * CH + k];
        const float* tp = &d_tpw[(size_t)e * 512];
        float v0 = u * tp[k];
        float v1 = u * tp[CH + k];
        float v2 = u * tp[2 * CH + k];
        float v3 = u * tp[3 * CH + k];
        acc[0] += shv[0] * v0;
        acc[1] += shv[1] * v1; acc[2] += shv[2] * v1; acc[3] += shv[3] * v1;
        acc[4] += shv[4] * v2; acc[5] += shv[5] * v2; acc[6] += shv[6] * v2;
        acc[7] += shv[7] * v2; acc[8] += shv[8] * v2;
        acc[9] += shv[9] * v3; acc[10] += shv[10] * v3; acc[11] += shv[11] * v3;
        acc[12] += shv[12] * v3; acc[13] += shv[13] * v3; acc[14] += shv[14] * v3;
        acc[15] += shv[15] * v3;
        __syncthreads();
    }
#pragma unroll
    for (int m = 0; m < 16; m++)
        d_msg[((size_t)n * 16 + m) * CH + k] = acc[m] * 0.1f;
}

// ---------------- A = msg @ W_lin[L(m)] / sqrt(128) ----------------
__global__ void k_wlin(int t, const float* __restrict__ W_lin) {
    const int mstart[4] = {0, 1, 4, 9};
    const int mcount[4] = {1, 3, 5, 7};
    int l = blockIdx.y;
    int nm = mcount[l], ms = mstart[l];
    extern __shared__ float sm[];
    float* Wsh = sm;           // 16384
    float* msh = sm + 16384;   // <= 56*128
    const float* W = W_lin + ((size_t)t * 4 + l) * CH * CH;
    int k = threadIdx.x;
    for (int i = k; i < CH * CH; i += 128) Wsh[i] = W[i];
    int n0 = blockIdx.x * 8;
    int rows = 8 * nm;
    for (int r = 0; r < rows; r++) {
        int node = n0 + r / nm, m = ms + r % nm;
        msh[r * CH + k] = d_msg[((size_t)node * 16 + m) * CH + k];
    }
    __syncthreads();
    for (int rb = 0; rb < rows; rb += 8) {
        float acc[8] = {0.f, 0.f, 0.f, 0.f, 0.f, 0.f, 0.f, 0.f};
#pragma unroll 4
        for (int c = 0; c < CH; c++) {
            float w = Wsh[c * CH + k];
#pragma unroll
            for (int q = 0; q < 8; q++) acc[q] += msh[(rb + q) * CH + c] * w;
        }
#pragma unroll
        for (int q = 0; q < 8; q++) {
            int rr = rb + q;
            int node = n0 + rr / nm, m = ms + rr % nm;
            d_Amat[((size_t)node * 16 + m) * CH + k] = acc[q] * 0.08838834764831845f;
        }
    }
}

// ---------------- nonlinearity + prodlin + skip -> new node feats ----------
__global__ void k_final(int t, const float* __restrict__ Wp1,
                        const float* __restrict__ Wp2,
                        const float* __restrict__ Wp3,
                        const float* __restrict__ W_prodlin) {
    extern __shared__ float sm[];
    float* Wsh = sm;          // 16384
    float* bsh = sm + 16384;  // 16*128
    const float* Wp = W_prodlin + t * CH * CH;
    int k = threadIdx.x;
    for (int i = k; i < CH * CH; i += 128) Wsh[i] = Wp[i];
    int n0 = blockIdx.x * 16;
    for (int r = 0; r < 16; r++) {
        int n = n0 + r;
        const float* Arow = &d_Amat[(size_t)n * 16 * CH + k];
        float A0 = Arow[0];
        float inv2[4];
        inv2[0] = A0 * A0; inv2[1] = 0.f; inv2[2] = 0.f; inv2[3] = 0.f;
#pragma unroll
        for (int m = 1; m < 4; m++) { float a = Arow[m * CH]; inv2[1] += a * a; }
#pragma unroll
        for (int m = 4; m < 9; m++) { float a = Arow[m * CH]; inv2[2] += a * a; }
#pragma unroll
        for (int m = 9; m < 16; m++) { float a = Arow[m * CH]; inv2[3] += a * a; }
        int s = d_species[n];
        const float* p1 = Wp1 + ((size_t)t * NZ + s) * CH;
        const float* p2 = Wp2 + ((size_t)t * NZ + s) * 4 * CH;
        const float* p3 = Wp3 + ((size_t)t * NZ + s) * 4 * CH;
        float s2 = 0.f, s3v = 0.f;
#pragma unroll
        for (int l = 0; l < 4; l++) {
            s2 += p2[l * CH + k] * inv2[l];
            s3v += p3[l * CH + k] * inv2[l];
        }
        bsh[r * CH + k] = p1[k] * A0 + s2 + s3v * A0;
    }
    __syncthreads();
    float* nfo = (t == 0) ? d_nfB : d_nfA;
    for (int r = 0; r < 16; r++) {
        float acc = 0.f;
        const float* b = bsh + r * CH;
#pragma unroll 8
        for (int c = 0; c < CH; c++) acc += b[c] * Wsh[c * CH + k];
        nfo[(n0 + r) * CH + k] = acc * 0.08838834764831845f + d_scb[(n0 + r) * CH + k];
    }
}

// ---------------- graph mean pooling ----------------
__global__ void k_env(const int* __restrict__ batch_idx, float* __restrict__ out) {
    int tid = blockIdx.x * blockDim.x + threadIdx.x;
    if (tid >= NN * CH) return;
    int n = tid >> 7, k = tid & 127;
    int g = batch_idx[n];
    atomicAdd(&out[g * CH + k], d_nfA[tid]);
    if (k == 0) atomicAdd(&d_gcnt[g], 1.f);
}

__global__ void k_div(float* __restrict__ out) {
    int i = blockIdx.x * blockDim.x + threadIdx.x;
    if (i >= NG * CH) return;
    int g = i >> 7;
    out[i] /= fmaxf(d_gcnt[g], 1.f);
}

// ---------------- launcher ----------------
extern "C" void kernel_launch(void* const* d_in, const int* in_sizes, int n_in,
                              void* d_out, int out_size) {
    const float* x        = (const float*)d_in[0];
    const float* pos      = (const float*)d_in[1];
    const float* W_embed  = (const float*)d_in[2];
    const float* W_up     = (const float*)d_in[3];
    const float* Wr0      = (const float*)d_in[4];
    const float* Wr1      = (const float*)d_in[5];
    const float* Wr2      = (const float*)d_in[6];
    const float* Wr3      = (const float*)d_in[7];
    const float* W_lin    = (const float*)d_in[8];
    const float* W_skip   = (const float*)d_in[9];
    const float* Wp1      = (const float*)d_in[10];
    const float* Wp2      = (const float*)d_in[11];
    const float* Wp3      = (const float*)d_in[12];
    const float* W_prodlin= (const float*)d_in[13];
    const int*   edge_index = (const int*)d_in[14];
    const int*   batch_idx  = (const int*)d_in[15];
    float* out = (float*)d_out;

    const int SM_UP    = (16384 + 16 * CH) * 4;
    const int SM_SC    = (16384 + 16 * CH) * 4;
    const int SM_RAD   = (512 + 4096 + 4096 + 32768 + 32 + 256 + 256) * 4;
    const int SM_WLIN  = (16384 + 56 * CH) * 4;
    const int SM_FINAL = (16384 + 16 * CH) * 4;
    cudaFuncSetAttribute(k_up,     cudaFuncAttributeMaxDynamicSharedMemorySize, SM_UP);
    cudaFuncSetAttribute(k_sc,     cudaFuncAttributeMaxDynamicSharedMemorySize, SM_SC);
    cudaFuncSetAttribute(k_radial, cudaFuncAttributeMaxDynamicSharedMemorySize, SM_RAD);
    cudaFuncSetAttribute(k_wlin,   cudaFuncAttributeMaxDynamicSharedMemorySize, SM_WLIN);
    cudaFuncSetAttribute(k_final,  cudaFuncAttributeMaxDynamicSharedMemorySize, SM_FINAL);

    k_zero<<<(NN + 255) / 256, 256>>>();
    k_node_init<<<(NN * CH) / 256, 256>>>(x, W_embed);
    k_edge_geom<<<NE / 256, 256>>>(pos, edge_index);
    k_hist<<<NE / 256, 256>>>(edge_index);
    k_scan<<<1, 1024>>>();
    k_scatter<<<NE / 256, 256>>>(edge_index);
    k_sscatter<<<NN / 256, 256>>>();

    for (int t = 0; t < 2; t++) {
        k_up<<<NN / 16, 128, SM_UP>>>(t, W_up);
        k_sc<<<dim3(NN / 16, NZ), 128, SM_SC>>>(t, W_skip);
        k_radial<<<NE / 128, 256, SM_RAD>>>(t, Wr0, Wr1, Wr2, Wr3);
        k_gather<<<NN, 128>>>(edge_index);
        k_wlin<<<dim3(NN / 8, 4), 128, SM_WLIN>>>(t, W_lin);
        k_final<<<NN / 16, 128, SM_FINAL>>>(t, Wp1, Wp2, Wp3, W_prodlin);
    }

    cudaMemsetAsync(d_out, 0, (size_t)out_size * sizeof(float));
    k_env<<<(NN * CH) / 256, 256>>>(batch_idx, out);
    k_div<<<(NG * CH + 255) / 256, 256>>>(out);
}

// round 4
// speedup vs baseline: 1.3071x; 1.3071x over previous
#include <cuda_runtime.h>

#define NN 16384
#define NE 65536
#define NG 64
#define NZ 10
#define CH 128

typedef unsigned long long u64;

// ---------------- scratch (device globals; no allocations) ----------------
__device__ __align__(16) float d_sh[NE * 16];
__device__ __align__(16) float d_rad[NE * 8];
__device__ __align__(16) float d_tpw[(size_t)NE * 512];      // 128 MB
__device__ __align__(16) float d_up[NN * CH];
__device__ __align__(16) float d_scb[NN * CH];
__device__ __align__(16) float d_msg[(size_t)NN * 16 * CH];  // 128 MB
__device__ __align__(16) float d_Amat[(size_t)NN * 16 * CH];
__device__ __align__(16) float d_nfA[NN * CH];
__device__ __align__(16) float d_nfB[NN * CH];
__device__ int   d_species[NN];
__device__ int   d_count[NN];
__device__ int   d_offsets[NN + 1];
__device__ int   d_cursor[NN];
__device__ int   d_perm[NE];
__device__ int   d_scount[NZ];
__device__ int   d_soff[NZ + 1];
__device__ int   d_scursor[NZ];
__device__ int   d_sperm[NN];
__device__ float d_gcnt[NG];

__device__ __forceinline__ float silu(float x) {
    return x / (1.f + __expf(-x));
}

// ---- f32x2 packed math helpers ----
__device__ __forceinline__ u64 pk2(float a, float b) {
    u64 r; asm("mov.b64 %0, {%1, %2};" : "=l"(r) : "f"(a), "f"(b)); return r;
}
__device__ __forceinline__ void fma2(u64 &d, u64 a, u64 b) {
    asm("fma.rn.f32x2 %0, %1, %2, %0;" : "+l"(d) : "l"(a), "l"(b));
}
__device__ __forceinline__ u64 mul2(u64 a, u64 b) {
    u64 r; asm("mul.rn.f32x2 %0, %1, %2;" : "=l"(r) : "l"(a), "l"(b)); return r;
}
__device__ __forceinline__ float2 unpk(u64 v) {
    float2 r; asm("mov.b64 {%0, %1}, %2;" : "=f"(r.x), "=f"(r.y) : "l"(v)); return r;
}
__device__ __forceinline__ float hsum2(u64 v) {
    float2 s = unpk(v); return s.x + s.y;
}

// ---------------- init / zero ----------------
__global__ void k_zero() {
    int i = blockIdx.x * blockDim.x + threadIdx.x;
    if (i < NN) d_count[i] = 0;
    if (i < NZ) d_scount[i] = 0;
    if (i < NG) d_gcnt[i] = 0.f;
}

__global__ void k_node_init(const float* __restrict__ x,
                            const float* __restrict__ W_embed) {
    int tid = blockIdx.x * blockDim.x + threadIdx.x;
    if (tid >= NN * CH) return;
    int n = tid >> 7, k = tid & 127;
    const float* xr = x + n * NZ;
    int s = 0;
    float best = xr[0];
#pragma unroll
    for (int z = 1; z < NZ; z++) {
        float v = xr[z];
        if (v > best) { best = v; s = z; }
    }
    if (k == 0) {
        d_species[n] = s;
        atomicAdd(&d_scount[s], 1);
    }
    d_nfA[tid] = W_embed[s * CH + k] * 0.31622776601683794f;
}

// ---------------- edge geometry: SH + radial basis ----------------
__global__ void k_edge_geom(const float* __restrict__ pos,
                            const int* __restrict__ edge_index) {
    int e = blockIdx.x * blockDim.x + threadIdx.x;
    if (e >= NE) return;
    int j = edge_index[e];
    int i = edge_index[NE + e];
    float dx = pos[j * 3 + 0] - pos[i * 3 + 0];
    float dy = pos[j * 3 + 1] - pos[i * 3 + 1];
    float dz = pos[j * 3 + 2] - pos[i * 3 + 2];
    float r2 = dx * dx + dy * dy + dz * dz + 1e-12f;
    float r = sqrtf(r2);
    float inv = 1.f / r;
    float X = dx * inv, Y = dy * inv, Z = dz * inv;
    float x2 = X * X, y2 = Y * Y, z2 = Z * Z;

    const float s3 = 1.7320508075688772f;
    const float s15 = 3.872983346207417f;
    const float s5 = 2.23606797749979f;
    const float s35_8 = 2.091650066335189f;
    const float s105 = 10.246950765959598f;
    const float s21_8 = 1.6201851746019651f;
    const float s7 = 2.6457513110645907f;

    float sh[16];
    sh[0] = 1.f;
    sh[1] = s3 * X; sh[2] = s3 * Y; sh[3] = s3 * Z;
    sh[4] = s15 * X * Y;
    sh[5] = s15 * Y * Z;
    sh[6] = 0.5f * s5 * (3.f * z2 - 1.f);
    sh[7] = s15 * X * Z;
    sh[8] = 0.5f * s15 * (x2 - y2);
    sh[9] = s35_8 * Y * (3.f * x2 - y2);
    sh[10] = s105 * X * Y * Z;
    sh[11] = s21_8 * Y * (5.f * z2 - 1.f);
    sh[12] = 0.5f * s7 * Z * (5.f * z2 - 3.f);
    sh[13] = s21_8 * X * (5.f * z2 - 1.f);
    sh[14] = 0.5f * s105 * Z * (x2 - y2);
    sh[15] = s35_8 * X * (x2 - 3.f * y2);
#pragma unroll
    for (int q = 0; q < 4; q++)
        *(float4*)&d_sh[e * 16 + q * 4] = *(float4*)&sh[q * 4];

    float u = r * 0.2f;
    float u2 = u * u;
    float u5 = u2 * u2 * u;
    float f = 1.f - 21.f * u5 + 35.f * u5 * u - 15.f * u5 * u2;
    if (u >= 1.f) f = 0.f;
    float coef = 0.6324555320336759f * inv * f;
    float rad[8];
#pragma unroll
    for (int nb = 1; nb <= 8; nb++)
        rad[nb - 1] = coef * sinpif((float)nb * u);
    *(float4*)&d_rad[e * 8] = *(float4*)&rad[0];
    *(float4*)&d_rad[e * 8 + 4] = *(float4*)&rad[4];
}

// ---------------- CSR build ----------------
__global__ void k_hist(const int* __restrict__ edge_index) {
    int e = blockIdx.x * blockDim.x + threadIdx.x;
    if (e >= NE) return;
    atomicAdd(&d_count[edge_index[NE + e]], 1);
}

__global__ void k_scan() {
    __shared__ int sh[1024];
    int T = threadIdx.x;
    int base = T * 16;
    int loc[16];
    int s = 0;
#pragma unroll
    for (int q = 0; q < 16; q++) { loc[q] = d_count[base + q]; s += loc[q]; }
    sh[T] = s;
    __syncthreads();
    for (int off = 1; off < 1024; off <<= 1) {
        int v = (T >= off) ? sh[T - off] : 0;
        __syncthreads();
        sh[T] += v;
        __syncthreads();
    }
    int excl = sh[T] - s;
#pragma unroll
    for (int q = 0; q < 16; q++) {
        d_offsets[base + q] = excl;
        d_cursor[base + q] = excl;
        excl += loc[q];
    }
    if (T == 1023) d_offsets[NN] = sh[1023];
    if (T == 0) {
        int a = 0;
        for (int z = 0; z < NZ; z++) {
            d_soff[z] = a; d_scursor[z] = a; a += d_scount[z];
        }
        d_soff[NZ] = a;
    }
}

__global__ void k_scatter(const int* __restrict__ edge_index) {
    int e = blockIdx.x * blockDim.x + threadIdx.x;
    if (e >= NE) return;
    int i = edge_index[NE + e];
    int p = atomicAdd(&d_cursor[i], 1);
    d_perm[p] = e;
}

__global__ void k_sscatter() {
    int n = blockIdx.x * blockDim.x + threadIdx.x;
    if (n >= NN) return;
    int s = d_species[n];
    int p = atomicAdd(&d_scursor[s], 1);
    d_sperm[p] = n;
}

// ---------------- up = nf @ W_up / sqrt(128) ----------------
__global__ void __launch_bounds__(128) k_up(int t, const float* __restrict__ W_up) {
    extern __shared__ float sm[];
    float* Wsh = sm;           // 16384 floats
    float* msh = sm + 16384;   // 32 rows x 128
    int k = threadIdx.x;
    const float* W = W_up + t * CH * CH;
    for (int i = k; i < 4096; i += 128)
        ((float4*)Wsh)[i] = ((const float4*)W)[i];
    const float* nf = t ? d_nfB : d_nfA;
    int n0 = blockIdx.x * 32;
    for (int i = k; i < 1024; i += 128)
        ((float4*)msh)[i] = ((const float4*)nf)[n0 * 32 + i];
    __syncthreads();
    for (int h = 0; h < 2; h++) {
        u64 acc[16];
#pragma unroll
        for (int q = 0; q < 16; q++) acc[q] = 0ull;
        for (int c = 0; c < CH; c += 4) {
            u64 w01 = pk2(Wsh[c * CH + k], Wsh[(c + 1) * CH + k]);
            u64 w23 = pk2(Wsh[(c + 2) * CH + k], Wsh[(c + 3) * CH + k]);
#pragma unroll
            for (int q = 0; q < 16; q++) {
                ulonglong2 mv = *(const ulonglong2*)&msh[(h * 16 + q) * CH + c];
                fma2(acc[q], mv.x, w01);
                fma2(acc[q], mv.y, w23);
            }
        }
#pragma unroll
        for (int q = 0; q < 16; q++)
            d_up[(n0 + h * 16 + q) * CH + k] = hsum2(acc[q]) * 0.08838834764831845f;
    }
}

// ---------------- sc (species-bucketed skip) ----------------
__global__ void __launch_bounds__(128) k_sc(int t, const float* __restrict__ W_skip) {
    int z = blockIdx.y;
    int lo = d_soff[z], hi = d_soff[z + 1];
    int n0 = lo + blockIdx.x * 16;
    if (n0 >= hi) return;
    extern __shared__ float sm[];
    float* Wsh = sm;
    float* msh = sm + 16384;  // 16 rows
    __shared__ int offs[16];
    int k = threadIdx.x;
    const float* W = W_skip + ((size_t)t * NZ + z) * CH * CH;
    for (int i = k; i < 4096; i += 128)
        ((float4*)Wsh)[i] = ((const float4*)W)[i];
    int cnt = min(16, hi - n0);
    if (k < cnt) offs[k] = d_sperm[n0 + k] * CH;
    __syncthreads();
    const float* nf = t ? d_nfB : d_nfA;
    for (int i = k; i < cnt * 32; i += 128) {
        int r = i >> 5;
        ((float4*)msh)[i] = *(const float4*)(nf + offs[r] + ((i & 31) << 2));
    }
    __syncthreads();
    u64 acc[16];
#pragma unroll
    for (int q = 0; q < 16; q++) acc[q] = 0ull;
    for (int c = 0; c < CH; c += 4) {
        u64 w01 = pk2(Wsh[c * CH + k], Wsh[(c + 1) * CH + k]);
        u64 w23 = pk2(Wsh[(c + 2) * CH + k], Wsh[(c + 3) * CH + k]);
#pragma unroll
        for (int q = 0; q < 16; q++) {
            ulonglong2 mv = *(const ulonglong2*)&msh[q * CH + c];
            fma2(acc[q], mv.x, w01);
            fma2(acc[q], mv.y, w23);
        }
    }
    for (int q = 0; q < cnt; q++)
        d_scb[offs[q] + k] = hsum2(acc[q]) * 0.027950849718747372f;
}

// ---------------- radial MLP (per edge) -> tpw ----------------
__global__ void __launch_bounds__(256) k_radial(
    int t, const float* __restrict__ Wr0, const float* __restrict__ Wr1,
    const float* __restrict__ Wr2, const float* __restrict__ Wr3) {
    extern __shared__ float sm[];
    float* w0 = sm;              // 512
    float* w1 = w0 + 512;        // 4096
    float* w2 = w1 + 4096;       // 4096
    float* w3 = w2 + 4096;       // 32768
    float* radsh = w3 + 32768;   // 32
    float* hA = radsh + 32;      // 256
    float* hB = hA + 256;        // 256

    const float* W0 = Wr0 + t * 8 * 64;
    const float* W1 = Wr1 + t * 64 * 64;
    const float* W2 = Wr2 + t * 64 * 64;
    const float* W3 = Wr3 + t * 64 * 512;
    int tid = threadIdx.x;
    for (int i = tid; i < 128; i += 256) ((float4*)w0)[i] = ((const float4*)W0)[i];
    for (int i = tid; i < 1024; i += 256) ((float4*)w1)[i] = ((const float4*)W1)[i];
    for (int i = tid; i < 1024; i += 256) ((float4*)w2)[i] = ((const float4*)W2)[i];
    for (int i = tid; i < 8192; i += 256) ((float4*)w3)[i] = ((const float4*)W3)[i];
    __syncthreads();

    int eo = tid >> 6, o = tid & 63;
    int ebase0 = blockIdx.x * 128;
    const u64 scale2 = pk2(0.125f, 0.125f);
    for (int it = 0; it < 32; it++) {
        int ebase = ebase0 + it * 4;
        if (tid < 32) radsh[tid] = d_rad[(ebase + (tid >> 3)) * 8 + (tid & 7)];
        __syncthreads();
        // layer 0: 8 -> 64
        float acc = 0.f;
#pragma unroll
        for (int c = 0; c < 8; c++) acc += radsh[eo * 8 + c] * w0[c * 64 + o];
        hA[eo * 64 + o] = silu(acc * 0.3535533905932738f);
        __syncthreads();
        // layer 1: 64 -> 64 (f32x2)
        {
            u64 a2 = 0ull;
#pragma unroll
            for (int c = 0; c < 64; c += 4) {
                ulonglong2 hv = *(const ulonglong2*)&hA[eo * 64 + c];
                u64 wA = pk2(w1[c * 64 + o], w1[(c + 1) * 64 + o]);
                u64 wB = pk2(w1[(c + 2) * 64 + o], w1[(c + 3) * 64 + o]);
                fma2(a2, hv.x, wA);
                fma2(a2, hv.y, wB);
            }
            hB[eo * 64 + o] = silu(hsum2(a2) * 0.125f);
        }
        __syncthreads();
        // layer 2: 64 -> 64 (f32x2)
        {
            u64 a2 = 0ull;
#pragma unroll
            for (int c = 0; c < 64; c += 4) {
                ulonglong2 hv = *(const ulonglong2*)&hB[eo * 64 + c];
                u64 wA = pk2(w2[c * 64 + o], w2[(c + 1) * 64 + o]);
                u64 wB = pk2(w2[(c + 2) * 64 + o], w2[(c + 3) * 64 + o]);
                fma2(a2, hv.x, wA);
                fma2(a2, hv.y, wB);
            }
            hA[eo * 64 + o] = silu(hsum2(a2) * 0.125f);
        }
        __syncthreads();
        // layer 3: 64 -> 512, 8 outputs per thread (4 f32x2 accumulators)
        {
            u64 ap[4] = {0ull, 0ull, 0ull, 0ull};
#pragma unroll 4
            for (int c = 0; c < 64; c += 4) {
                float4 hv = *(const float4*)&hA[eo * 64 + c];
#pragma unroll
                for (int cc = 0; cc < 4; cc++) {
                    float hvv = (cc == 0) ? hv.x : (cc == 1) ? hv.y : (cc == 2) ? hv.z : hv.w;
                    u64 h2 = pk2(hvv, hvv);
                    const ulonglong2* wr = (const ulonglong2*)&w3[(c + cc) * 512 + 8 * o];
                    ulonglong2 wa = wr[0];
                    ulonglong2 wb = wr[1];
                    fma2(ap[0], h2, wa.x);
                    fma2(ap[1], h2, wa.y);
                    fma2(ap[2], h2, wb.x);
                    fma2(ap[3], h2, wb.y);
                }
            }
            size_t e = (size_t)(ebase + eo);
            ulonglong2* outp = (ulonglong2*)&d_tpw[e * 512 + 8 * o];
            outp[0] = make_ulonglong2(mul2(ap[0], scale2), mul2(ap[1], scale2));
            outp[1] = make_ulonglong2(mul2(ap[2], scale2), mul2(ap[3], scale2));
        }
        __syncthreads();
    }
}

// ---------------- gather: msg[n,m,k] (CSR, shuffles, no barriers) --------
__global__ void __launch_bounds__(128) k_gather(const int* __restrict__ edge_index) {
    int n = blockIdx.x;
    int k = threadIdx.x, lane = k & 31;
    int lo = d_offsets[n], hi = d_offsets[n + 1];
    float acc[16];
#pragma unroll
    for (int m = 0; m < 16; m++) acc[m] = 0.f;
    for (int p = lo; p < hi; p++) {
        int e = d_perm[p];
        float shl = (lane < 16) ? d_sh[e * 16 + lane] : 0.f;
        int j = edge_index[e];
        float u = d_up[j * CH + k];
        const float* tp = d_tpw + (size_t)e * 512;
        float v0 = u * tp[k];
        float v1 = u * tp[CH + k];
        float v2 = u * tp[2 * CH + k];
        float v3 = u * tp[3 * CH + k];
        acc[0] += __shfl_sync(0xffffffffu, shl, 0) * v0;
#pragma unroll
        for (int m = 1; m < 4; m++) acc[m] += __shfl_sync(0xffffffffu, shl, m) * v1;
#pragma unroll
        for (int m = 4; m < 9; m++) acc[m] += __shfl_sync(0xffffffffu, shl, m) * v2;
#pragma unroll
        for (int m = 9; m < 16; m++) acc[m] += __shfl_sync(0xffffffffu, shl, m) * v3;
    }
#pragma unroll
    for (int m = 0; m < 16; m++)
        d_msg[((size_t)n * 16 + m) * CH + k] = acc[m] * 0.1f;
}

// ---------------- A = msg @ W_lin[L(m)] / sqrt(128) ----------------
__global__ void __launch_bounds__(128) k_wlin(int t, const float* __restrict__ W_lin) {
    int l = blockIdx.y;
    const int ms = (l == 0) ? 0 : (l == 1) ? 1 : (l == 2) ? 4 : 9;
    const int nm = (l == 0) ? 1 : (l == 1) ? 3 : (l == 2) ? 5 : 7;
    extern __shared__ float sm[];
    float* Wsh = sm;
    float* msh = sm + 16384;  // up to 56 rows
    __shared__ int offs[56];
    int k = threadIdx.x;
    const float* W = W_lin + ((size_t)(t * 4 + l)) * CH * CH;
    for (int i = k; i < 4096; i += 128)
        ((float4*)Wsh)[i] = ((const float4*)W)[i];
    int n0 = blockIdx.x * 8;
    int rows = 8 * nm;
    if (k < rows)
        offs[k] = ((n0 + k / nm) * 16 + ms + k % nm) * CH;
    __syncthreads();
    for (int i = k; i < rows * 32; i += 128) {
        int r = i >> 5;
        ((float4*)msh)[i] = *(const float4*)(d_msg + offs[r] + ((i & 31) << 2));
    }
    __syncthreads();
    for (int rb = 0; rb < rows; rb += 8) {
        u64 acc[8];
#pragma unroll
        for (int q = 0; q < 8; q++) acc[q] = 0ull;
        for (int c = 0; c < CH; c += 4) {
            u64 w01 = pk2(Wsh[c * CH + k], Wsh[(c + 1) * CH + k]);
            u64 w23 = pk2(Wsh[(c + 2) * CH + k], Wsh[(c + 3) * CH + k]);
#pragma unroll
            for (int q = 0; q < 8; q++) {
                ulonglong2 mv = *(const ulonglong2*)&msh[(rb + q) * CH + c];
                fma2(acc[q], mv.x, w01);
                fma2(acc[q], mv.y, w23);
            }
        }
#pragma unroll
        for (int q = 0; q < 8; q++)
            d_Amat[offs[rb + q] + k] = hsum2(acc[q]) * 0.08838834764831845f;
    }
}

// ---------------- nonlinearity + prodlin + skip -> new node feats ----------
__global__ void __launch_bounds__(128) k_final(int t, const float* __restrict__ Wp1,
                        const float* __restrict__ Wp2,
                        const float* __restrict__ Wp3,
                        const float* __restrict__ W_prodlin) {
    extern __shared__ float sm[];
    float* Wsh = sm;          // 16384
    float* bsh = sm + 16384;  // 16*128
    const float* Wp = W_prodlin + t * CH * CH;
    int k = threadIdx.x;
    for (int i = k; i < 4096; i += 128)
        ((float4*)Wsh)[i] = ((const float4*)Wp)[i];
    int n0 = blockIdx.x * 16;
    for (int r = 0; r < 16; r++) {
        int n = n0 + r;
        const float* Ar = d_Amat + (size_t)n * 16 * CH;
        float A0 = Ar[k];
        float i0 = A0 * A0, i1 = 0.f, i2 = 0.f, i3 = 0.f;
#pragma unroll
        for (int m = 1; m < 4; m++) { float a = Ar[m * CH + k]; i1 += a * a; }
#pragma unroll
        for (int m = 4; m < 9; m++) { float a = Ar[m * CH + k]; i2 += a * a; }
#pragma unroll
        for (int m = 9; m < 16; m++) { float a = Ar[m * CH + k]; i3 += a * a; }
        int s = d_species[n];
        const float* p1 = Wp1 + ((size_t)t * NZ + s) * CH;
        const float* p2 = Wp2 + ((size_t)t * NZ + s) * 4 * CH;
        const float* p3 = Wp3 + ((size_t)t * NZ + s) * 4 * CH;
        float s2 = p2[k] * i0 + p2[CH + k] * i1 + p2[2 * CH + k] * i2 + p2[3 * CH + k] * i3;
        float s3v = p3[k] * i0 + p3[CH + k] * i1 + p3[2 * CH + k] * i2 + p3[3 * CH + k] * i3;
        bsh[r * CH + k] = p1[k] * A0 + s2 + s3v * A0;
    }
    __syncthreads();
    u64 acc[16];
#pragma unroll
    for (int q = 0; q < 16; q++) acc[q] = 0ull;
    for (int c = 0; c < CH; c += 4) {
        u64 w01 = pk2(Wsh[c * CH + k], Wsh[(c + 1) * CH + k]);
        u64 w23 = pk2(Wsh[(c + 2) * CH + k], Wsh[(c + 3) * CH + k]);
#pragma unroll
        for (int q = 0; q < 16; q++) {
            ulonglong2 mv = *(const ulonglong2*)&bsh[q * CH + c];
            fma2(acc[q], mv.x, w01);
            fma2(acc[q], mv.y, w23);
        }
    }
    float* nfo = (t == 0) ? d_nfB : d_nfA;
#pragma unroll
    for (int q = 0; q < 16; q++)
        nfo[(n0 + q) * CH + k] = hsum2(acc[q]) * 0.08838834764831845f +
                                 d_scb[(n0 + q) * CH + k];
}

// ---------------- graph mean pooling ----------------
__global__ void k_env(const int* __restrict__ batch_idx, float* __restrict__ out) {
    int tid = blockIdx.x * blockDim.x + threadIdx.x;
    if (tid >= NN * CH) return;
    int n = tid >> 7, k = tid & 127;
    int g = batch_idx[n];
    atomicAdd(&out[g * CH + k], d_nfA[tid]);
    if (k == 0) atomicAdd(&d_gcnt[g], 1.f);
}

__global__ void k_div(float* __restrict__ out) {
    int i = blockIdx.x * blockDim.x + threadIdx.x;
    if (i >= NG * CH) return;
    int g = i >> 7;
    out[i] /= fmaxf(d_gcnt[g], 1.f);
}

// ---------------- launcher ----------------
extern "C" void kernel_launch(void* const* d_in, const int* in_sizes, int n_in,
                              void* d_out, int out_size) {
    const float* x        = (const float*)d_in[0];
    const float* pos      = (const float*)d_in[1];
    const float* W_embed  = (const float*)d_in[2];
    const float* W_up     = (const float*)d_in[3];
    const float* Wr0      = (const float*)d_in[4];
    const float* Wr1      = (const float*)d_in[5];
    const float* Wr2      = (const float*)d_in[6];
    const float* Wr3      = (const float*)d_in[7];
    const float* W_lin    = (const float*)d_in[8];
    const float* W_skip   = (const float*)d_in[9];
    const float* Wp1      = (const float*)d_in[10];
    const float* Wp2      = (const float*)d_in[11];
    const float* Wp3      = (const float*)d_in[12];
    const float* W_prodlin= (const float*)d_in[13];
    const int*   edge_index = (const int*)d_in[14];
    const int*   batch_idx  = (const int*)d_in[15];
    float* out = (float*)d_out;

    const int SM_UP    = (16384 + 4096) * 4;
    const int SM_SC    = (16384 + 2048) * 4;
    const int SM_RAD   = (512 + 4096 + 4096 + 32768 + 32 + 256 + 256) * 4;
    const int SM_WLIN  = (16384 + 56 * CH) * 4;
    const int SM_FINAL = (16384 + 2048) * 4;
    cudaFuncSetAttribute(k_up,     cudaFuncAttributeMaxDynamicSharedMemorySize, SM_UP);
    cudaFuncSetAttribute(k_sc,     cudaFuncAttributeMaxDynamicSharedMemorySize, SM_SC);
    cudaFuncSetAttribute(k_radial, cudaFuncAttributeMaxDynamicSharedMemorySize, SM_RAD);
    cudaFuncSetAttribute(k_wlin,   cudaFuncAttributeMaxDynamicSharedMemorySize, SM_WLIN);
    cudaFuncSetAttribute(k_final,  cudaFuncAttributeMaxDynamicSharedMemorySize, SM_FINAL);

    k_zero<<<(NN + 255) / 256, 256>>>();
    k_node_init<<<(NN * CH) / 256, 256>>>(x, W_embed);
    k_edge_geom<<<NE / 256, 256>>>(pos, edge_index);
    k_hist<<<NE / 256, 256>>>(edge_index);
    k_scan<<<1, 1024>>>();
    k_scatter<<<NE / 256, 256>>>(edge_index);
    k_sscatter<<<NN / 256, 256>>>();

    for (int t = 0; t < 2; t++) {
        k_up<<<NN / 32, 128, SM_UP>>>(t, W_up);
        k_sc<<<dim3(NN / 16, NZ), 128, SM_SC>>>(t, W_skip);
        k_radial<<<NE / 128, 256, SM_RAD>>>(t, Wr0, Wr1, Wr2, Wr3);
        k_gather<<<NN, 128>>>(edge_index);
        k_wlin<<<dim3(NN / 8, 4), 128, SM_WLIN>>>(t, W_lin);
        k_final<<<NN / 16, 128, SM_FINAL>>>(t, Wp1, Wp2, Wp3, W_prodlin);
    }

    cudaMemsetAsync(d_out, 0, (size_t)out_size * sizeof(float));
    k_env<<<(NN * CH) / 256, 256>>>(batch_idx, out);
    k_div<<<(NG * CH + 255) / 256, 256>>>(out);
}

// round 5
// speedup vs baseline: 1.9872x; 1.5203x over previous
#include <cuda_runtime.h>

#define NN 16384
#define NE 65536
#define NG 64
#define NZ 10
#define CH 128

typedef unsigned long long u64;

// ---------------- scratch (device globals; no allocations) ----------------
__device__ __align__(16) float d_sh[NE * 16];
__device__ __align__(16) float d_rad[NE * 8];
__device__ __align__(16) float d_tpw[(size_t)NE * 512];
__device__ __align__(16) float d_up[NN * CH];
__device__ __align__(16) float d_scb[NN * CH];
__device__ __align__(16) float d_msg[(size_t)NN * 16 * CH];
__device__ __align__(16) float d_Amat[(size_t)NN * 16 * CH];
__device__ __align__(16) float d_nfA[NN * CH];
__device__ __align__(16) float d_nfB[NN * CH];
__device__ int   d_species[NN];
__device__ int   d_count[NN];
__device__ int   d_offsets[NN + 1];
__device__ int   d_cursor[NN];
__device__ int   d_perm[NE];
__device__ int   d_scount[NZ];
__device__ int   d_soff[NZ + 1];
__device__ int   d_scursor[NZ];
__device__ int   d_sperm[NN];
__device__ float d_gcnt[NG];

__device__ __forceinline__ float silu(float x) {
    return x / (1.f + __expf(-x));
}

// ---- f32x2 packed math helpers ----
__device__ __forceinline__ u64 pk2(float a, float b) {
    u64 r; asm("mov.b64 %0, {%1, %2};" : "=l"(r) : "f"(a), "f"(b)); return r;
}
__device__ __forceinline__ void fma2(u64 &d, u64 a, u64 b) {
    asm("fma.rn.f32x2 %0, %1, %2, %0;" : "+l"(d) : "l"(a), "l"(b));
}
__device__ __forceinline__ u64 mul2(u64 a, u64 b) {
    u64 r; asm("mul.rn.f32x2 %0, %1, %2;" : "=l"(r) : "l"(a), "l"(b)); return r;
}
__device__ __forceinline__ float2 unpk(u64 v) {
    float2 r; asm("mov.b64 {%0, %1}, %2;" : "=f"(r.x), "=f"(r.y) : "l"(v)); return r;
}
__device__ __forceinline__ float hsum2(u64 v) {
    float2 s = unpk(v); return s.x + s.y;
}

// store W[c][k] (row-major CHxCH) into pair-interleaved smem:
// Wp[(c>>1)*256 + k*2 + (c&1)]  -> LDS.64 at [pp*256 + 2k] yields (W[2pp][k],W[2pp+1][k])
__device__ __forceinline__ void load_w_pairs(float* Wp, const float* W, int tid, int nthr) {
    for (int i = tid; i < 4096; i += nthr) {
        float4 v = ((const float4*)W)[i];
        int c = i >> 5, kq = (i & 31) << 2;
        float* dst = &Wp[(c >> 1) * 256 + (c & 1)];
        dst[(kq + 0) * 2] = v.x;
        dst[(kq + 1) * 2] = v.y;
        dst[(kq + 2) * 2] = v.z;
        dst[(kq + 3) * 2] = v.w;
    }
}

// ---------------- init / zero ----------------
__global__ void k_zero() {
    int i = blockIdx.x * blockDim.x + threadIdx.x;
    if (i < NN) d_count[i] = 0;
    if (i < NZ) d_scount[i] = 0;
    if (i < NG) d_gcnt[i] = 0.f;
}

__global__ void k_node_init(const float* __restrict__ x,
                            const float* __restrict__ W_embed) {
    int tid = blockIdx.x * blockDim.x + threadIdx.x;
    if (tid >= NN * CH) return;
    int n = tid >> 7, k = tid & 127;
    const float* xr = x + n * NZ;
    int s = 0;
    float best = xr[0];
#pragma unroll
    for (int z = 1; z < NZ; z++) {
        float v = xr[z];
        if (v > best) { best = v; s = z; }
    }
    if (k == 0) {
        d_species[n] = s;
        atomicAdd(&d_scount[s], 1);
    }
    d_nfA[tid] = W_embed[s * CH + k] * 0.31622776601683794f;
}

// ---------------- edge geometry: SH + radial basis ----------------
__global__ void k_edge_geom(const float* __restrict__ pos,
                            const int* __restrict__ edge_index) {
    int e = blockIdx.x * blockDim.x + threadIdx.x;
    if (e >= NE) return;
    int j = edge_index[e];
    int i = edge_index[NE + e];
    float dx = pos[j * 3 + 0] - pos[i * 3 + 0];
    float dy = pos[j * 3 + 1] - pos[i * 3 + 1];
    float dz = pos[j * 3 + 2] - pos[i * 3 + 2];
    float r2 = dx * dx + dy * dy + dz * dz + 1e-12f;
    float r = sqrtf(r2);
    float inv = 1.f / r;
    float X = dx * inv, Y = dy * inv, Z = dz * inv;
    float x2 = X * X, y2 = Y * Y, z2 = Z * Z;

    const float s3 = 1.7320508075688772f;
    const float s15 = 3.872983346207417f;
    const float s5 = 2.23606797749979f;
    const float s35_8 = 2.091650066335189f;
    const float s105 = 10.246950765959598f;
    const float s21_8 = 1.6201851746019651f;
    const float s7 = 2.6457513110645907f;

    float sh[16];
    sh[0] = 1.f;
    sh[1] = s3 * X; sh[2] = s3 * Y; sh[3] = s3 * Z;
    sh[4] = s15 * X * Y;
    sh[5] = s15 * Y * Z;
    sh[6] = 0.5f * s5 * (3.f * z2 - 1.f);
    sh[7] = s15 * X * Z;
    sh[8] = 0.5f * s15 * (x2 - y2);
    sh[9] = s35_8 * Y * (3.f * x2 - y2);
    sh[10] = s105 * X * Y * Z;
    sh[11] = s21_8 * Y * (5.f * z2 - 1.f);
    sh[12] = 0.5f * s7 * Z * (5.f * z2 - 3.f);
    sh[13] = s21_8 * X * (5.f * z2 - 1.f);
    sh[14] = 0.5f * s105 * Z * (x2 - y2);
    sh[15] = s35_8 * X * (x2 - 3.f * y2);
#pragma unroll
    for (int q = 0; q < 4; q++)
        *(float4*)&d_sh[e * 16 + q * 4] = *(float4*)&sh[q * 4];

    float u = r * 0.2f;
    float u2 = u * u;
    float u5 = u2 * u2 * u;
    float f = 1.f - 21.f * u5 + 35.f * u5 * u - 15.f * u5 * u2;
    if (u >= 1.f) f = 0.f;
    float coef = 0.6324555320336759f * inv * f;
    float rad[8];
#pragma unroll
    for (int nb = 1; nb <= 8; nb++)
        rad[nb - 1] = coef * sinpif((float)nb * u);
    *(float4*)&d_rad[e * 8] = *(float4*)&rad[0];
    *(float4*)&d_rad[e * 8 + 4] = *(float4*)&rad[4];
}

// ---------------- CSR build ----------------
__global__ void k_hist(const int* __restrict__ edge_index) {
    int e = blockIdx.x * blockDim.x + threadIdx.x;
    if (e >= NE) return;
    atomicAdd(&d_count[edge_index[NE + e]], 1);
}

__global__ void k_scan() {
    __shared__ int sh[1024];
    int T = threadIdx.x;
    int base = T * 16;
    int loc[16];
    int s = 0;
#pragma unroll
    for (int q = 0; q < 16; q++) { loc[q] = d_count[base + q]; s += loc[q]; }
    sh[T] = s;
    __syncthreads();
    for (int off = 1; off < 1024; off <<= 1) {
        int v = (T >= off) ? sh[T - off] : 0;
        __syncthreads();
        sh[T] += v;
        __syncthreads();
    }
    int excl = sh[T] - s;
#pragma unroll
    for (int q = 0; q < 16; q++) {
        d_offsets[base + q] = excl;
        d_cursor[base + q] = excl;
        excl += loc[q];
    }
    if (T == 1023) d_offsets[NN] = sh[1023];
    if (T == 0) {
        int a = 0;
        for (int z = 0; z < NZ; z++) {
            d_soff[z] = a; d_scursor[z] = a; a += d_scount[z];
        }
        d_soff[NZ] = a;
    }
}

__global__ void k_scatter(const int* __restrict__ edge_index) {
    int e = blockIdx.x * blockDim.x + threadIdx.x;
    if (e >= NE) return;
    int i = edge_index[NE + e];
    int p = atomicAdd(&d_cursor[i], 1);
    d_perm[p] = e;
}

__global__ void k_sscatter() {
    int n = blockIdx.x * blockDim.x + threadIdx.x;
    if (n >= NN) return;
    int s = d_species[n];
    int p = atomicAdd(&d_scursor[s], 1);
    d_sperm[p] = n;
}

// ---------------- up = nf @ W_up / sqrt(128) ----------------
__global__ void __launch_bounds__(256) k_up(int t, const float* __restrict__ W_up) {
    extern __shared__ float sm[];
    float* Wsh = sm;           // 16384 pair-interleaved
    float* msh = sm + 16384;   // 32 rows x 128
    int tid = threadIdx.x;
    int k = tid & 127, h = tid >> 7;
    load_w_pairs(Wsh, W_up + t * CH * CH, tid, 256);
    const float* nf = t ? d_nfB : d_nfA;
    int n0 = blockIdx.x * 32;
    for (int i = tid; i < 1024; i += 256)
        ((float4*)msh)[i] = ((const float4*)nf)[n0 * 32 + i];
    __syncthreads();
    u64 acc[16];
#pragma unroll
    for (int q = 0; q < 16; q++) acc[q] = 0ull;
    for (int pp = 0; pp < 64; pp += 2) {
        u64 w01 = *(const u64*)&Wsh[pp * 256 + 2 * k];
        u64 w23 = *(const u64*)&Wsh[(pp + 1) * 256 + 2 * k];
#pragma unroll
        for (int q = 0; q < 16; q++) {
            ulonglong2 mv = *(const ulonglong2*)&msh[(h * 16 + q) * CH + 2 * pp];
            fma2(acc[q], mv.x, w01);
            fma2(acc[q], mv.y, w23);
        }
    }
#pragma unroll
    for (int q = 0; q < 16; q++)
        d_up[(n0 + h * 16 + q) * CH + k] = hsum2(acc[q]) * 0.08838834764831845f;
}

// ---------------- sc (species-bucketed skip) ----------------
__global__ void __launch_bounds__(128) k_sc(int t, const float* __restrict__ W_skip) {
    int z = blockIdx.y;
    int lo = d_soff[z], hi = d_soff[z + 1];
    int n0 = lo + blockIdx.x * 16;
    if (n0 >= hi) return;
    extern __shared__ float sm[];
    float* Wsh = sm;
    float* msh = sm + 16384;
    __shared__ int offs[16];
    int k = threadIdx.x;
    load_w_pairs(Wsh, W_skip + ((size_t)t * NZ + z) * CH * CH, k, 128);
    int cnt = min(16, hi - n0);
    if (k < cnt) offs[k] = d_sperm[n0 + k] * CH;
    __syncthreads();
    const float* nf = t ? d_nfB : d_nfA;
    for (int i = k; i < cnt * 32; i += 128) {
        int r = i >> 5;
        ((float4*)msh)[i] = *(const float4*)(nf + offs[r] + ((i & 31) << 2));
    }
    __syncthreads();
    u64 acc[16];
#pragma unroll
    for (int q = 0; q < 16; q++) acc[q] = 0ull;
    for (int pp = 0; pp < 64; pp += 2) {
        u64 w01 = *(const u64*)&Wsh[pp * 256 + 2 * k];
        u64 w23 = *(const u64*)&Wsh[(pp + 1) * 256 + 2 * k];
#pragma unroll
        for (int q = 0; q < 16; q++) {
            ulonglong2 mv = *(const ulonglong2*)&msh[q * CH + 2 * pp];
            fma2(acc[q], mv.x, w01);
            fma2(acc[q], mv.y, w23);
        }
    }
    for (int q = 0; q < cnt; q++)
        d_scb[offs[q] + k] = hsum2(acc[q]) * 0.027950849718747372f;
}

// ---------------- radial MLP: 512 threads, 16-edge tiles ----------------
// smem floats: w0p 512 | w1p 4096 | w2p 4096 | w3 32768 | radT 128 | hA 1024 |
//              hB 1024 | hAT 1280 (stride 20)   total 44928 fl = 175.5 KB
__global__ void __launch_bounds__(512) k_radial(
    int t, const float* __restrict__ Wr0, const float* __restrict__ Wr1,
    const float* __restrict__ Wr2, const float* __restrict__ Wr3) {
    extern __shared__ float sm[];
    float* w0p = sm;             // 512
    float* w1p = w0p + 512;      // 4096
    float* w2p = w1p + 4096;     // 4096
    float* w3  = w2p + 4096;     // 32768
    float* radT = w3 + 32768;    // 128
    float* hA  = radT + 128;     // 1024
    float* hB  = hA + 1024;      // 1024
    float* hAT = hB + 1024;      // 64*20 = 1280

    const float* W0 = Wr0 + t * 8 * 64;
    const float* W1 = Wr1 + t * 64 * 64;
    const float* W2 = Wr2 + t * 64 * 64;
    const float* W3 = Wr3 + t * 64 * 512;
    int tid = threadIdx.x;

    // pair-interleave w0/w1/w2: wp[(c>>1)*128 + o*2 + (c&1)]
    for (int i = tid; i < 128; i += 512) {
        float4 v = ((const float4*)W0)[i];
        int c = i >> 4, o4 = (i & 15) << 2;
        float* dst = &w0p[(c >> 1) * 128 + (c & 1)];
        dst[(o4 + 0) * 2] = v.x; dst[(o4 + 1) * 2] = v.y;
        dst[(o4 + 2) * 2] = v.z; dst[(o4 + 3) * 2] = v.w;
    }
    for (int i = tid; i < 1024; i += 512) {
        float4 v = ((const float4*)W1)[i];
        int c = i >> 4, o4 = (i & 15) << 2;
        float* dst = &w1p[(c >> 1) * 128 + (c & 1)];
        dst[(o4 + 0) * 2] = v.x; dst[(o4 + 1) * 2] = v.y;
        dst[(o4 + 2) * 2] = v.z; dst[(o4 + 3) * 2] = v.w;
    }
    for (int i = tid; i < 1024; i += 512) {
        float4 v = ((const float4*)W2)[i];
        int c = i >> 4, o4 = (i & 15) << 2;
        float* dst = &w2p[(c >> 1) * 128 + (c & 1)];
        dst[(o4 + 0) * 2] = v.x; dst[(o4 + 1) * 2] = v.y;
        dst[(o4 + 2) * 2] = v.z; dst[(o4 + 3) * 2] = v.w;
    }
    for (int i = tid; i < 8192; i += 512)
        ((float4*)w3)[i] = ((const float4*)W3)[i];

    int o  = tid & 63;           // layers 0-2: output column
    int ep = tid >> 6;           // 0..7 -> local edges 2ep, 2ep+1
    int e0 = 2 * ep, e1 = 2 * ep + 1;
    int og = tid & 127;          // layer 3: output group (4 outs)
    int eq = tid >> 7;           // 0..3  -> local edges 4eq..4eq+3
    const u64 scale2 = pk2(0.125f, 0.125f);

    for (int tile = 0; tile < 8; tile++) {
        int ebase = blockIdx.x * 128 + tile * 16;
        // stage radial features (16 edges x 8 = 128 contiguous floats)
        if (tid < 32)
            ((float4*)radT)[tid] = ((const float4*)(d_rad + (size_t)ebase * 8))[tid];
        __syncthreads();
        // layer 0: 8 -> 64
        {
            u64 a = 0ull, b = 0ull;
#pragma unroll
            for (int cp = 0; cp < 4; cp++) {
                u64 w = *(const u64*)&w0p[cp * 128 + o * 2];
                u64 r0 = *(const u64*)&radT[e0 * 8 + cp * 2];
                u64 r1 = *(const u64*)&radT[e1 * 8 + cp * 2];
                fma2(a, r0, w);
                fma2(b, r1, w);
            }
            hA[e0 * 64 + o] = silu(hsum2(a) * 0.3535533905932738f);
            hA[e1 * 64 + o] = silu(hsum2(b) * 0.3535533905932738f);
        }
        __syncthreads();
        // layer 1: 64 -> 64
        {
            u64 a = 0ull, b = 0ull;
#pragma unroll 8
            for (int cp = 0; cp < 32; cp++) {
                u64 w = *(const u64*)&w1p[cp * 128 + o * 2];
                u64 h0 = *(const u64*)&hA[e0 * 64 + cp * 2];
                u64 h1 = *(const u64*)&hA[e1 * 64 + cp * 2];
                fma2(a, h0, w);
                fma2(b, h1, w);
            }
            hB[e0 * 64 + o] = silu(hsum2(a) * 0.125f);
            hB[e1 * 64 + o] = silu(hsum2(b) * 0.125f);
        }
        __syncthreads();
        // layer 2: 64 -> 64, output transposed into hAT[c][edge] (stride 20)
        {
            u64 a = 0ull, b = 0ull;
#pragma unroll 8
            for (int cp = 0; cp < 32; cp++) {
                u64 w = *(const u64*)&w2p[cp * 128 + o * 2];
                u64 h0 = *(const u64*)&hB[e0 * 64 + cp * 2];
                u64 h1 = *(const u64*)&hB[e1 * 64 + cp * 2];
                fma2(a, h0, w);
                fma2(b, h1, w);
            }
            hAT[o * 20 + e0] = silu(hsum2(a) * 0.125f);
            hAT[o * 20 + e1] = silu(hsum2(b) * 0.125f);
        }
        __syncthreads();
        // layer 3: 64 -> 512; thread owns 4 outputs (og*4..+3) x 4 edges (4eq..+3)
        {
            u64 a01[4], a23[4];
#pragma unroll
            for (int q = 0; q < 4; q++) { a01[q] = 0ull; a23[q] = 0ull; }
#pragma unroll 4
            for (int c = 0; c < 64; c++) {
                ulonglong2 w = *(const ulonglong2*)&w3[c * 512 + og * 4];
                float4 hv = *(const float4*)&hAT[c * 20 + eq * 4];
                u64 h0 = pk2(hv.x, hv.x);
                u64 h1 = pk2(hv.y, hv.y);
                u64 h2 = pk2(hv.z, hv.z);
                u64 h3 = pk2(hv.w, hv.w);
                fma2(a01[0], h0, w.x); fma2(a23[0], h0, w.y);
                fma2(a01[1], h1, w.x); fma2(a23[1], h1, w.y);
                fma2(a01[2], h2, w.x); fma2(a23[2], h2, w.y);
                fma2(a01[3], h3, w.x); fma2(a23[3], h3, w.y);
            }
#pragma unroll
            for (int q = 0; q < 4; q++) {
                size_t ge = (size_t)(ebase + eq * 4 + q);
                ulonglong2 outv;
                outv.x = mul2(a01[q], scale2);
                outv.y = mul2(a23[q], scale2);
                *(ulonglong2*)&d_tpw[ge * 512 + og * 4] = outv;
            }
        }
        __syncthreads();
    }
}

// ---------------- gather: msg[n,m,k] (CSR, staged headers) --------
__global__ void __launch_bounds__(128) k_gather(const int* __restrict__ edge_index) {
    int n = blockIdx.x;
    int k = threadIdx.x, lane = k & 31;
    int lo = d_offsets[n], hi = d_offsets[n + 1];
    __shared__ int se[32];
    __shared__ int sj[32];
    float acc[16];
#pragma unroll
    for (int m = 0; m < 16; m++) acc[m] = 0.f;
    for (int base = lo; base < hi; base += 32) {
        int cnt = min(32, hi - base);
        if (k < cnt) {
            int e = d_perm[base + k];
            se[k] = e;
            sj[k] = edge_index[e];
        }
        __syncthreads();
#pragma unroll 2
        for (int p = 0; p < cnt; p++) {
            int e = se[p];
            int j = sj[p];
            float shl = (lane < 16) ? d_sh[e * 16 + lane] : 0.f;
            float u = d_up[j * CH + k];
            const float* tp = d_tpw + (size_t)e * 512;
            float v0 = u * tp[k];
            float v1 = u * tp[CH + k];
            float v2 = u * tp[2 * CH + k];
            float v3 = u * tp[3 * CH + k];
            acc[0] += __shfl_sync(0xffffffffu, shl, 0) * v0;
#pragma unroll
            for (int m = 1; m < 4; m++) acc[m] += __shfl_sync(0xffffffffu, shl, m) * v1;
#pragma unroll
            for (int m = 4; m < 9; m++) acc[m] += __shfl_sync(0xffffffffu, shl, m) * v2;
#pragma unroll
            for (int m = 9; m < 16; m++) acc[m] += __shfl_sync(0xffffffffu, shl, m) * v3;
        }
        __syncthreads();
    }
#pragma unroll
    for (int m = 0; m < 16; m++)
        d_msg[((size_t)n * 16 + m) * CH + k] = acc[m] * 0.1f;
}

// ---------------- A = msg @ W_lin[L(m)] / sqrt(128) ----------------
__global__ void __launch_bounds__(256) k_wlin(int t, const float* __restrict__ W_lin) {
    int l = blockIdx.y;
    const int ms = (l == 0) ? 0 : (l == 1) ? 1 : (l == 2) ? 4 : 9;
    const int nm = (l == 0) ? 1 : (l == 1) ? 3 : (l == 2) ? 5 : 7;
    extern __shared__ float sm[];
    float* Wsh = sm;
    float* msh = sm + 16384;
    __shared__ int offs[56];
    int tid = threadIdx.x;
    int k = tid & 127, h = tid >> 7;
    load_w_pairs(Wsh, W_lin + ((size_t)(t * 4 + l)) * CH * CH, tid, 256);
    int n0 = blockIdx.x * 8;
    int rows = 8 * nm;
    if (tid < rows)
        offs[tid] = ((n0 + tid / nm) * 16 + ms + tid % nm) * CH;
    __syncthreads();
    for (int i = tid; i < rows * 32; i += 256) {
        int r = i >> 5;
        ((float4*)msh)[i] = *(const float4*)(d_msg + offs[r] + ((i & 31) << 2));
    }
    __syncthreads();
    for (int rb = h * 8; rb < rows; rb += 16) {
        u64 acc[8];
#pragma unroll
        for (int q = 0; q < 8; q++) acc[q] = 0ull;
        for (int pp = 0; pp < 64; pp += 2) {
            u64 w01 = *(const u64*)&Wsh[pp * 256 + 2 * k];
            u64 w23 = *(const u64*)&Wsh[(pp + 1) * 256 + 2 * k];
#pragma unroll
            for (int q = 0; q < 8; q++) {
                ulonglong2 mv = *(const ulonglong2*)&msh[(rb + q) * CH + 2 * pp];
                fma2(acc[q], mv.x, w01);
                fma2(acc[q], mv.y, w23);
            }
        }
#pragma unroll
        for (int q = 0; q < 8; q++)
            d_Amat[offs[rb + q] + k] = hsum2(acc[q]) * 0.08838834764831845f;
    }
}

// ---------------- nonlinearity + prodlin + skip -> new node feats ----------
__global__ void __launch_bounds__(256) k_final(int t, const float* __restrict__ Wp1,
                        const float* __restrict__ Wp2,
                        const float* __restrict__ Wp3,
                        const float* __restrict__ W_prodlin) {
    extern __shared__ float sm[];
    float* Wsh = sm;          // 16384 pair-interleaved
    float* bsh = sm + 16384;  // 16*128
    int tid = threadIdx.x;
    int k = tid & 127, h = tid >> 7;
    load_w_pairs(Wsh, W_prodlin + t * CH * CH, tid, 256);
    int n0 = blockIdx.x * 16;
    for (int rr = 0; rr < 8; rr++) {
        int r = h * 8 + rr;
        int n = n0 + r;
        const float* Ar = d_Amat + (size_t)n * 16 * CH;
        float A0 = Ar[k];
        float i0 = A0 * A0, i1 = 0.f, i2 = 0.f, i3 = 0.f;
#pragma unroll
        for (int m = 1; m < 4; m++) { float a = Ar[m * CH + k]; i1 += a * a; }
#pragma unroll
        for (int m = 4; m < 9; m++) { float a = Ar[m * CH + k]; i2 += a * a; }
#pragma unroll
        for (int m = 9; m < 16; m++) { float a = Ar[m * CH + k]; i3 += a * a; }
        int s = d_species[n];
        const float* p1 = Wp1 + ((size_t)t * NZ + s) * CH;
        const float* p2 = Wp2 + ((size_t)t * NZ + s) * 4 * CH;
        const float* p3 = Wp3 + ((size_t)t * NZ + s) * 4 * CH;
        float s2 = p2[k] * i0 + p2[CH + k] * i1 + p2[2 * CH + k] * i2 + p2[3 * CH + k] * i3;
        float s3v = p3[k] * i0 + p3[CH + k] * i1 + p3[2 * CH + k] * i2 + p3[3 * CH + k] * i3;
        bsh[r * CH + k] = p1[k] * A0 + s2 + s3v * A0;
    }
    __syncthreads();
    u64 acc[8];
#pragma unroll
    for (int q = 0; q < 8; q++) acc[q] = 0ull;
    for (int pp = 0; pp < 64; pp += 2) {
        u64 w01 = *(const u64*)&Wsh[pp * 256 + 2 * k];
        u64 w23 = *(const u64*)&Wsh[(pp + 1) * 256 + 2 * k];
#pragma unroll
        for (int q = 0; q < 8; q++) {
            ulonglong2 mv = *(const ulonglong2*)&bsh[(h * 8 + q) * CH + 2 * pp];
            fma2(acc[q], mv.x, w01);
            fma2(acc[q], mv.y, w23);
        }
    }
    float* nfo = (t == 0) ? d_nfB : d_nfA;
#pragma unroll
    for (int q = 0; q < 8; q++)
        nfo[(n0 + h * 8 + q) * CH + k] = hsum2(acc[q]) * 0.08838834764831845f +
                                         d_scb[(n0 + h * 8 + q) * CH + k];
}

// ---------------- graph mean pooling ----------------
__global__ void k_env(const int* __restrict__ batch_idx, float* __restrict__ out) {
    int tid = blockIdx.x * blockDim.x + threadIdx.x;
    if (tid >= NN * CH) return;
    int n = tid >> 7, k = tid & 127;
    int g = batch_idx[n];
    atomicAdd(&out[g * CH + k], d_nfA[tid]);
    if (k == 0) atomicAdd(&d_gcnt[g], 1.f);
}

__global__ void k_div(float* __restrict__ out) {
    int i = blockIdx.x * blockDim.x + threadIdx.x;
    if (i >= NG * CH) return;
    int g = i >> 7;
    out[i] /= fmaxf(d_gcnt[g], 1.f);
}

// ---------------- launcher ----------------
extern "C" void kernel_launch(void* const* d_in, const int* in_sizes, int n_in,
                              void* d_out, int out_size) {
    const float* x        = (const float*)d_in[0];
    const float* pos      = (const float*)d_in[1];
    const float* W_embed  = (const float*)d_in[2];
    const float* W_up     = (const float*)d_in[3];
    const float* Wr0      = (const float*)d_in[4];
    const float* Wr1      = (const float*)d_in[5];
    const float* Wr2      = (const float*)d_in[6];
    const float* Wr3      = (const float*)d_in[7];
    const float* W_lin    = (const float*)d_in[8];
    const float* W_skip   = (const float*)d_in[9];
    const float* Wp1      = (const float*)d_in[10];
    const float* Wp2      = (const float*)d_in[11];
    const float* Wp3      = (const float*)d_in[12];
    const float* W_prodlin= (const float*)d_in[13];
    const int*   edge_index = (const int*)d_in[14];
    const int*   batch_idx  = (const int*)d_in[15];
    float* out = (float*)d_out;

    const int SM_UP    = (16384 + 4096) * 4;
    const int SM_SC    = (16384 + 2048) * 4;
    const int SM_RAD   = 44928 * 4;  // 175.5 KB
    const int SM_WLIN  = (16384 + 56 * CH) * 4;
    const int SM_FINAL = (16384 + 2048) * 4;
    cudaFuncSetAttribute(k_up,     cudaFuncAttributeMaxDynamicSharedMemorySize, SM_UP);
    cudaFuncSetAttribute(k_sc,     cudaFuncAttributeMaxDynamicSharedMemorySize, SM_SC);
    cudaFuncSetAttribute(k_radial, cudaFuncAttributeMaxDynamicSharedMemorySize, SM_RAD);
    cudaFuncSetAttribute(k_wlin,   cudaFuncAttributeMaxDynamicSharedMemorySize, SM_WLIN);
    cudaFuncSetAttribute(k_final,  cudaFuncAttributeMaxDynamicSharedMemorySize, SM_FINAL);

    k_zero<<<(NN + 255) / 256, 256>>>();
    k_node_init<<<(NN * CH) / 256, 256>>>(x, W_embed);
    k_edge_geom<<<NE / 256, 256>>>(pos, edge_index);
    // radial t=0 placed 4th so ncu (-s 5 -c 1 window) profiles it
    k_radial<<<NE / 128, 512, SM_RAD>>>(0, Wr0, Wr1, Wr2, Wr3);
    k_hist<<<NE / 256, 256>>>(edge_index);
    k_scan<<<1, 1024>>>();
    k_scatter<<<NE / 256, 256>>>(edge_index);
    k_sscatter<<<NN / 256, 256>>>();

    for (int t = 0; t < 2; t++) {
        k_up<<<NN / 32, 256, SM_UP>>>(t, W_up);
        k_sc<<<dim3(NN / 16, NZ), 128, SM_SC>>>(t, W_skip);
        if (t == 1)
            k_radial<<<NE / 128, 512, SM_RAD>>>(t, Wr0, Wr1, Wr2, Wr3);
        k_gather<<<NN, 128>>>(edge_index);
        k_wlin<<<dim3(NN / 8, 4), 256, SM_WLIN>>>(t, W_lin);
        k_final<<<NN / 16, 256, SM_FINAL>>>(t, Wp1, Wp2, Wp3, W_prodlin);
    }

    cudaMemsetAsync(d_out, 0, (size_t)out_size * sizeof(float));
    k_env<<<(NN * CH) / 256, 256>>>(batch_idx, out);
    k_div<<<(NG * CH + 255) / 256, 256>>>(out);
}